// round 2
// baseline (speedup 1.0000x reference)
#include <cuda_runtime.h>

// LIF scan over T=8 timesteps, N = 4,194,304 independent spatial elements.
//   mem = mem*0.25*(1-spike) + x[t]; spike = (mem >= 0.5)
// Streaming kernel: 128 MiB read + 128 MiB write, zero data reuse.
// R2: streaming cache hints (__ldcs/__stcs, evict-first) + persistent
// grid-stride launch sized to one full wave (kills wave-transition tail).

#define DECAY  0.25f
#define THRESH 0.5f

static constexpr int T = 8;

__global__ __launch_bounds__(256) void lif_scan_kernel(
    const float4* __restrict__ x, float4* __restrict__ out, int n4)
{
    const int stride = gridDim.x * blockDim.x;
    for (int i = blockIdx.x * blockDim.x + threadIdx.x; i < n4; i += stride) {
        // Front-batch all 8 independent loads for MLP=8. Streaming (evict-first):
        // no reuse, keep L2 from retaining dead lines.
        float4 xv[T];
#pragma unroll
        for (int t = 0; t < T; t++) {
            xv[t] = __ldcs(&x[(size_t)t * n4 + i]);
        }

        float4 mem   = make_float4(0.f, 0.f, 0.f, 0.f);
        float4 spike = make_float4(0.f, 0.f, 0.f, 0.f);

#pragma unroll
        for (int t = 0; t < T; t++) {
            mem.x = mem.x * (DECAY * (1.0f - spike.x)) + xv[t].x;
            mem.y = mem.y * (DECAY * (1.0f - spike.y)) + xv[t].y;
            mem.z = mem.z * (DECAY * (1.0f - spike.z)) + xv[t].z;
            mem.w = mem.w * (DECAY * (1.0f - spike.w)) + xv[t].w;
            spike.x = (mem.x >= THRESH) ? 1.0f : 0.0f;
            spike.y = (mem.y >= THRESH) ? 1.0f : 0.0f;
            spike.z = (mem.z >= THRESH) ? 1.0f : 0.0f;
            spike.w = (mem.w >= THRESH) ? 1.0f : 0.0f;
            __stcs(&out[(size_t)t * n4 + i], spike);
        }
    }
}

extern "C" void kernel_launch(void* const* d_in, const int* in_sizes, int n_in,
                              void* d_out, int out_size)
{
    const float* x = (const float*)d_in[0];
    float* out = (float*)d_out;

    const int total = in_sizes[0];       // T * N
    const int n = total / T;             // elements per timestep (4,194,304)
    const int n4 = n / 4;                // float4 count per timestep (1,048,576)

    const int threads = 256;
    // Persistent: ~one full wave. 152 SMs * 8 blocks/SM (32 regs, 256 thr -> occ cap)
    int blocks = 152 * 8;                // 1216 blocks, grid-stride covers n4
    int needed = (n4 + threads - 1) / threads;
    if (blocks > needed) blocks = needed;

    lif_scan_kernel<<<blocks, threads>>>(
        (const float4*)x, (float4*)out, n4);
}

// round 3
// speedup vs baseline: 1.0522x; 1.0522x over previous
#include <cuda_runtime.h>

// LIF scan over T=8 timesteps, N = 4,194,304 independent spatial elements.
//   mem = mem*0.25*(1-spike) + x[t]; spike = (mem >= 0.5)
// Pure streaming: 128 MiB read + 128 MiB write, zero reuse -> DRAM-bound.
// R3: back to flat one-element-per-thread launch (R2's persistent grid-stride
// cost 48 regs / 52% occ -> reverted). Only change vs R1: streaming cache
// hints (__ldcs evict-first loads, __stcs stores) to cut dead-line retention
// in L2 across graph replays.

#define DECAY  0.25f
#define THRESH 0.5f

static constexpr int T = 8;

__global__ __launch_bounds__(256) void lif_scan_kernel(
    const float4* __restrict__ x, float4* __restrict__ out, int n4)
{
    int i = blockIdx.x * blockDim.x + threadIdx.x;
    if (i >= n4) return;

    // 8 independent streaming loads (evict-first: zero reuse).
    float4 xv[T];
#pragma unroll
    for (int t = 0; t < T; t++) {
        xv[t] = __ldcs(&x[(size_t)t * n4 + i]);
    }

    float4 mem   = make_float4(0.f, 0.f, 0.f, 0.f);
    float4 spike = make_float4(0.f, 0.f, 0.f, 0.f);

#pragma unroll
    for (int t = 0; t < T; t++) {
        mem.x = mem.x * (DECAY * (1.0f - spike.x)) + xv[t].x;
        mem.y = mem.y * (DECAY * (1.0f - spike.y)) + xv[t].y;
        mem.z = mem.z * (DECAY * (1.0f - spike.z)) + xv[t].z;
        mem.w = mem.w * (DECAY * (1.0f - spike.w)) + xv[t].w;
        spike.x = (mem.x >= THRESH) ? 1.0f : 0.0f;
        spike.y = (mem.y >= THRESH) ? 1.0f : 0.0f;
        spike.z = (mem.z >= THRESH) ? 1.0f : 0.0f;
        spike.w = (mem.w >= THRESH) ? 1.0f : 0.0f;
        __stcs(&out[(size_t)t * n4 + i], spike);
    }
}

extern "C" void kernel_launch(void* const* d_in, const int* in_sizes, int n_in,
                              void* d_out, int out_size)
{
    const float* x = (const float*)d_in[0];
    float* out = (float*)d_out;

    const int total = in_sizes[0];       // T * N
    const int n = total / T;             // elements per timestep (4,194,304)
    const int n4 = n / 4;                // float4 count per timestep (1,048,576)

    const int threads = 256;
    const int blocks = (n4 + threads - 1) / threads;

    lif_scan_kernel<<<blocks, threads>>>(
        (const float4*)x, (float4*)out, n4);
}